// round 3
// baseline (speedup 1.0000x reference)
#include <cuda_runtime.h>
#include <math.h>

// ---------------------------------------------------------------------------
// MSDeformableAttention — GB300 (sm_103a)
//
// Pipeline:
//   1) sgemm_bias: v   = value @ vp_w + vp_b            -> scratch V  [B*LV, 256]
//   2) sgemm_bias: so  = query @ so_w + so_b            -> scratch SO [B*LQ, 256]
//   3) sgemm_bias: awl = query @ aw_w + aw_b            -> scratch AW [B*LQ, 128]
//   4) softmax16 : softmax over each head's 16 logits (in place on AW)
//   5) sample    : bilinear gather + weighted sum       -> scratch ACC [B*LQ, 256]
//   6) sgemm_bias: out = ACC @ op_w + op_b              -> d_out
//
// Shapes are compile-time constants (from the reference):
//   B=8, LQ=1024, LV=13294, D=256, H=8, HD=32, L=4, P=4
//   levels (h,w,start): (100,100,0) (50,50,10000) (25,25,12500) (13,13,13125)
// ---------------------------------------------------------------------------

namespace cfg {
constexpr int B  = 8;
constexpr int LQ = 1024;
constexpr int LV = 13294;
constexpr int D  = 256;
constexpr int H  = 8;
constexpr int HD = 32;

constexpr size_t SZ_V   = (size_t)B * LV * D;    // 27,226,112
constexpr size_t SZ_SO  = (size_t)B * LQ * 256;  //  2,097,152
constexpr size_t SZ_AW  = (size_t)B * LQ * 128;  //  1,048,576
constexpr size_t SZ_ACC = (size_t)B * LQ * D;    //  2,097,152

constexpr size_t OFF_V   = 0;
constexpr size_t OFF_SO  = OFF_V  + SZ_V;
constexpr size_t OFF_AW  = OFF_SO + SZ_SO;
constexpr size_t OFF_ACC = OFF_AW + SZ_AW;
constexpr size_t SZ_TOT  = OFF_ACC + SZ_ACC;     // ~32.5M floats (~130 MB, bss)
}  // namespace cfg

__device__ float g_scratch[cfg::SZ_TOT];

// ---------------------------------------------------------------------------
// SGEMM with bias: C[M,N] = A[M,K] @ B[K,N] + bias[N]
// 128x128 tile, BK=8, 256 threads, 8x8 register microtile.
// Requires: K % 8 == 0, N % 128 == 0, 16B-aligned pointers. M is guarded.
// ---------------------------------------------------------------------------
__global__ __launch_bounds__(256, 2) void sgemm_bias_kernel(
    const float* __restrict__ A, const float* __restrict__ Bm,
    const float* __restrict__ bias, float* __restrict__ C,
    int M, int N, int K)
{
    __shared__ float As[8][128];
    __shared__ float Bs[8][128];

    const int tid  = threadIdx.x;
    const int row0 = blockIdx.y * 128;
    const int col0 = blockIdx.x * 128;
    const int tx   = tid & 15;   // along N (16)
    const int ty   = tid >> 4;   // along M (16)

    float acc[8][8];
#pragma unroll
    for (int i = 0; i < 8; i++)
#pragma unroll
        for (int j = 0; j < 8; j++) acc[i][j] = 0.0f;

    // Global-load mapping
    const int a_row = tid >> 1;          // 0..127
    const int a_col = (tid & 1) * 4;     // 0 or 4
    const int b_row = tid >> 5;          // 0..7
    const int b_col = (tid & 31) * 4;    // 0..124

    const bool a_ok = (row0 + a_row) < M;
    const float* Aptr = A + (size_t)(row0 + a_row) * K + a_col;
    const float* Bptr = Bm + (size_t)b_row * N + col0 + b_col;

    for (int k0 = 0; k0 < K; k0 += 8) {
        float4 av = a_ok ? *(const float4*)(Aptr + k0)
                         : make_float4(0.f, 0.f, 0.f, 0.f);
        float4 bv = *(const float4*)(Bptr + (size_t)k0 * N);

        As[a_col + 0][a_row] = av.x;
        As[a_col + 1][a_row] = av.y;
        As[a_col + 2][a_row] = av.z;
        As[a_col + 3][a_row] = av.w;
        *(float4*)&Bs[b_row][b_col] = bv;
        __syncthreads();

#pragma unroll
        for (int kk = 0; kk < 8; kk++) {
            float ar[8], br[8];
            *(float4*)&ar[0] = *(const float4*)&As[kk][ty * 8];
            *(float4*)&ar[4] = *(const float4*)&As[kk][ty * 8 + 4];
            *(float4*)&br[0] = *(const float4*)&Bs[kk][tx * 8];
            *(float4*)&br[4] = *(const float4*)&Bs[kk][tx * 8 + 4];
#pragma unroll
            for (int i = 0; i < 8; i++)
#pragma unroll
                for (int j = 0; j < 8; j++)
                    acc[i][j] = fmaf(ar[i], br[j], acc[i][j]);
        }
        __syncthreads();
    }

    // Bias (per output column of this thread)
    float bj[8];
#pragma unroll
    for (int j = 0; j < 8; j++) bj[j] = bias[col0 + tx * 8 + j];

#pragma unroll
    for (int i = 0; i < 8; i++) {
        int r = row0 + ty * 8 + i;
        if (r < M) {
            float* Cp = C + (size_t)r * N + col0 + tx * 8;
            float4 o0, o1;
            o0.x = acc[i][0] + bj[0]; o0.y = acc[i][1] + bj[1];
            o0.z = acc[i][2] + bj[2]; o0.w = acc[i][3] + bj[3];
            o1.x = acc[i][4] + bj[4]; o1.y = acc[i][5] + bj[5];
            o1.z = acc[i][6] + bj[6]; o1.w = acc[i][7] + bj[7];
            *(float4*)(Cp + 0) = o0;
            *(float4*)(Cp + 4) = o1;
        }
    }
}

// ---------------------------------------------------------------------------
// Softmax over 16 logits per (b,q,h), in place on AW [B*LQ, 128]
// ---------------------------------------------------------------------------
__global__ __launch_bounds__(256) void softmax16_kernel(float* __restrict__ aw)
{
    int t = blockIdx.x * 256 + threadIdx.x;       // one per (bq, h)
    if (t >= cfg::B * cfg::LQ * cfg::H) return;
    float* p = aw + (size_t)(t >> 3) * 128 + (t & 7) * 16;

    float v[16];
    float m = -1e30f;
#pragma unroll
    for (int i = 0; i < 16; i++) { v[i] = p[i]; m = fmaxf(m, v[i]); }
    float s = 0.f;
#pragma unroll
    for (int i = 0; i < 16; i++) { v[i] = expf(v[i] - m); s += v[i]; }
    float inv = 1.0f / s;
#pragma unroll
    for (int i = 0; i < 16; i++) p[i] = v[i] * inv;
}

// ---------------------------------------------------------------------------
// Sampling: one warp per (b, q, h); lane = head-dim channel.
// Every corner gather is a contiguous 32-float (128 B) warp load.
// ---------------------------------------------------------------------------
__global__ __launch_bounds__(256) void sample_kernel(
    const float* __restrict__ ref,   // [B, LQ, 4, 2]
    const float* __restrict__ v,     // [B, LV, H, HD]
    const float* __restrict__ so,    // [B*LQ, 256]
    const float* __restrict__ aw,    // [B*LQ, 128] (softmaxed)
    float* __restrict__ acc_out)     // [B*LQ, 256]
{
    const int w    = blockIdx.x * 8 + (threadIdx.x >> 5);
    const int lane = threadIdx.x & 31;
    const int h    = w & 7;
    const int bq   = w >> 3;           // b*LQ + q
    const int b    = bq >> 10;

    const float* so_p  = so  + (size_t)bq * 256 + h * 32;
    const float* aw_p  = aw  + (size_t)bq * 128 + h * 16;
    const float* ref_p = ref + (size_t)bq * 8;
    const float* vb    = v + (size_t)b * cfg::LV * cfg::D + h * cfg::HD + lane;

    const int LHW[4]   = {100, 50, 25, 13};
    const int LSTART[4] = {0, 10000, 12500, 13125};

    float acc = 0.0f;
#pragma unroll
    for (int l = 0; l < 4; l++) {
        const int   Wl = LHW[l];           // square levels: H==W
        const int   Hl = LHW[l];
        const float Wf = (float)Wl;
        const float Hf = (float)Hl;
        const float bx = ref_p[l * 2 + 0] * Wf - 0.5f;  // loc_x*W - 0.5
        const float by = ref_p[l * 2 + 1] * Hf - 0.5f;
        const float* base = vb + (size_t)LSTART[l] * cfg::D;

#pragma unroll
        for (int p = 0; p < 4; p++) {
            const float x  = bx + so_p[(l * 4 + p) * 2 + 0];
            const float y  = by + so_p[(l * 4 + p) * 2 + 1];
            const float wt = aw_p[l * 4 + p];

            const float x0f = floorf(x), y0f = floorf(y);
            const int   ix0 = (int)x0f,  iy0 = (int)y0f;
            const float fx = x - x0f,    fy = y - y0f;

            const bool vx0 = (ix0 >= 0)     && (ix0 < Wl);
            const bool vx1 = (ix0 + 1 >= 0) && (ix0 + 1 < Wl);
            const bool vy0 = (iy0 >= 0)     && (iy0 < Hl);
            const bool vy1 = (iy0 + 1 >= 0) && (iy0 + 1 < Hl);

            float v00 = 0.f, v01 = 0.f, v10 = 0.f, v11 = 0.f;
            if (vy0) {
                const float* r0 = base + (size_t)(iy0 * Wl) * cfg::D;
                if (vx0) v00 = __ldg(r0 + (size_t)ix0 * cfg::D);
                if (vx1) v01 = __ldg(r0 + (size_t)(ix0 + 1) * cfg::D);
            }
            if (vy1) {
                const float* r1 = base + (size_t)((iy0 + 1) * Wl) * cfg::D;
                if (vx0) v10 = __ldg(r1 + (size_t)ix0 * cfg::D);
                if (vx1) v11 = __ldg(r1 + (size_t)(ix0 + 1) * cfg::D);
            }

            const float top = v00 * (1.f - fx) + v01 * fx;
            const float bot = v10 * (1.f - fx) + v11 * fx;
            acc = fmaf(wt, top * (1.f - fy) + bot * fy, acc);
        }
    }
    acc_out[(size_t)bq * 256 + h * 32 + lane] = acc;
}

// ---------------------------------------------------------------------------
// Launch
// ---------------------------------------------------------------------------
extern "C" void kernel_launch(void* const* d_in, const int* in_sizes, int n_in,
                              void* d_out, int out_size)
{
    const float* query = (const float*)d_in[0];   // [8,1024,256]
    const float* refp  = (const float*)d_in[1];   // [8,1024,4,2]
    const float* value = (const float*)d_in[2];   // [8,13294,256]
    // d_in[3] = value_spatial_shapes (compile-time constant; ignored)
    const float* so_w  = (const float*)d_in[4];   // [256,256]
    const float* so_b  = (const float*)d_in[5];   // [256]
    const float* aw_w  = (const float*)d_in[6];   // [256,128]
    const float* aw_b  = (const float*)d_in[7];   // [128]
    const float* vp_w  = (const float*)d_in[8];   // [256,256]
    const float* vp_b  = (const float*)d_in[9];   // [256]
    const float* op_w  = (const float*)d_in[10];  // [256,256]
    const float* op_b  = (const float*)d_in[11];  // [256]
    float* out = (float*)d_out;                   // [8,1024,256]

    float* scratch = nullptr;
    cudaGetSymbolAddress((void**)&scratch, g_scratch);
    float* sV   = scratch + cfg::OFF_V;
    float* sSO  = scratch + cfg::OFF_SO;
    float* sAW  = scratch + cfg::OFF_AW;
    float* sACC = scratch + cfg::OFF_ACC;

    const int MQ = cfg::B * cfg::LQ;      // 8192
    const int MV = cfg::B * cfg::LV;      // 106352

    // 1) v = value @ vp_w + vp_b
    {
        dim3 grid(256 / 128, (MV + 127) / 128);
        sgemm_bias_kernel<<<grid, 256>>>(value, vp_w, vp_b, sV, MV, 256, 256);
    }
    // 2) so = query @ so_w + so_b
    {
        dim3 grid(256 / 128, MQ / 128);
        sgemm_bias_kernel<<<grid, 256>>>(query, so_w, so_b, sSO, MQ, 256, 256);
    }
    // 3) aw logits = query @ aw_w + aw_b
    {
        dim3 grid(128 / 128, MQ / 128);
        sgemm_bias_kernel<<<grid, 256>>>(query, aw_w, aw_b, sAW, MQ, 128, 256);
    }
    // 4) softmax over 16 logits per (b,q,h)
    {
        int total = cfg::B * cfg::LQ * cfg::H;   // 65536
        softmax16_kernel<<<(total + 255) / 256, 256>>>(sAW);
    }
    // 5) bilinear sampling + weighted sum
    {
        int warps = cfg::B * cfg::LQ * cfg::H;   // 65536 warps
        sample_kernel<<<warps / 8, 256>>>(refp, sV, sSO, sAW, sACC);
    }
    // 6) out = ACC @ op_w + op_b
    {
        dim3 grid(256 / 128, MQ / 128);
        sgemm_bias_kernel<<<grid, 256>>>(sACC, op_w, op_b, out, MQ, 256, 256);
    }
}

// round 8
// speedup vs baseline: 1.6111x; 1.6111x over previous
#include <cuda_runtime.h>
#include <math.h>
#include <stdint.h>

// ---------------------------------------------------------------------------
// MSDeformableAttention — GB300 (plain sm_103 target: tcgen05 unavailable,
// legacy mma.sync tf32 tensor path)
//
//   0) transpose vp_w / [so_w|aw_w] -> [N,K] K-major scratch; concat bias
//   1) tf32_gemm: v    = value @ vp_w + vp_b          -> V [B*LV, 256]
//   2) tf32_gemm: soaw = query @ [so_w | aw_w] + bias -> SOAW [B*LQ, 384]
//   3) sample: in-warp softmax + bilinear gather      -> ACC [B*LQ, 256]
//   4) ffma sgemm: out = ACC @ op_w + op_b  (op_w used UNTRANSPOSED, [K,N])
//
// B=8, LQ=1024, LV=13294, D=256, H=8, HD=32, L=4, P=4
// levels (h=w,start): (100,0) (50,10000) (25,12500) (13,13125)
// ---------------------------------------------------------------------------

namespace cfg {
constexpr int B  = 8;
constexpr int LQ = 1024;
constexpr int LV = 13294;
constexpr int D  = 256;
constexpr int H  = 8;

constexpr size_t SZ_V    = (size_t)B * LV * D;      // 27,226,112
constexpr size_t SZ_SOAW = (size_t)B * LQ * 384;
constexpr size_t SZ_ACC  = (size_t)B * LQ * D;
constexpr size_t SZ_VPT  = 256 * 256;
constexpr size_t SZ_SAWT = 384 * 256;
constexpr size_t SZ_BSA  = 384;

constexpr size_t OFF_V    = 0;
constexpr size_t OFF_SOAW = OFF_V    + SZ_V;
constexpr size_t OFF_ACC  = OFF_SOAW + SZ_SOAW;
constexpr size_t OFF_VPT  = OFF_ACC  + SZ_ACC;
constexpr size_t OFF_SAWT = OFF_VPT  + SZ_VPT;
constexpr size_t OFF_BSA  = OFF_SAWT + SZ_SAWT;
constexpr size_t SZ_TOT   = OFF_BSA  + SZ_BSA;      // ~32.6M floats (~130 MB bss)
}  // namespace cfg

__device__ float g_scratch[cfg::SZ_TOT];

// ---------------------------------------------------------------------------
__device__ __forceinline__ uint32_t f2tf32(float x) {
    uint32_t u;
    asm("cvt.rna.tf32.f32 %0, %1;" : "=r"(u) : "f"(x));
    return u;
}

__device__ __forceinline__ void mma_tf32(float d[4], const uint32_t a[4],
                                         const uint32_t b[2]) {
    asm volatile(
        "mma.sync.aligned.m16n8k8.row.col.f32.tf32.tf32.f32 "
        "{%0,%1,%2,%3}, {%4,%5,%6,%7}, {%8,%9}, {%0,%1,%2,%3};"
        : "+f"(d[0]), "+f"(d[1]), "+f"(d[2]), "+f"(d[3])
        : "r"(a[0]), "r"(a[1]), "r"(a[2]), "r"(a[3]), "r"(b[0]), "r"(b[1]));
}

// ---------------------------------------------------------------------------
// Weight transpose: out[c][r] = in[r][c]   (out is [C,R] row-major)
// ---------------------------------------------------------------------------
__global__ void transpose_kernel(const float* __restrict__ in,
                                 float* __restrict__ out, int R, int C)
{
    __shared__ float t[32][33];
    int bx = blockIdx.x * 32, by = blockIdx.y * 32;
    int x = bx + threadIdx.x;
#pragma unroll
    for (int i = 0; i < 32; i += 8) {
        int y = by + threadIdx.y + i;
        if (y < R && x < C) t[threadIdx.y + i][threadIdx.x] = in[(size_t)y * C + x];
    }
    __syncthreads();
    int x2 = by + threadIdx.x;
#pragma unroll
    for (int i = 0; i < 32; i += 8) {
        int y2 = bx + threadIdx.y + i;
        if (y2 < C && x2 < R) out[(size_t)y2 * R + x2] = t[threadIdx.x][threadIdx.y + i];
    }
}

__global__ void concat_bias_kernel(const float* __restrict__ b0,
                                   const float* __restrict__ b1,
                                   float* __restrict__ out)
{
    int t = threadIdx.x;                 // 384 threads
    out[t] = (t < 256) ? b0[t] : b1[t - 256];
}

// ---------------------------------------------------------------------------
// tf32 mma.sync GEMM with bias: C[M,N] = A[M,K] @ Bt[N,K]^T + bias[N]
// 128x128 CTA, BK=16 double-buffered, 256 threads (8 warps, 64x32 each).
// Requires K%16==0, N%128==0; M guarded.
// ---------------------------------------------------------------------------
__global__ __launch_bounds__(256, 2) void tf32_gemm_bias(
    const float* __restrict__ A, const float* __restrict__ Bt,
    const float* __restrict__ bias, float* __restrict__ C,
    int M, int N, int K)
{
    __shared__ uint32_t As[2][16][132];
    __shared__ uint32_t Bs[2][16][132];

    const int tid  = threadIdx.x;
    const int wid  = tid >> 5;
    const int lane = tid & 31;
    const int g    = lane >> 2;   // 0..7
    const int c    = lane & 3;    // 0..3
    const int row0 = blockIdx.y * 128;
    const int col0 = blockIdx.x * 128;
    const int wm   = (wid >> 2) * 64;   // warp m-offset (0/64)
    const int wn   = (wid & 3) * 32;    // warp n-offset (0/32/64/96)

    float acc[4][4][4];
#pragma unroll
    for (int mt = 0; mt < 4; mt++)
#pragma unroll
        for (int nt = 0; nt < 4; nt++)
#pragma unroll
            for (int r = 0; r < 4; r++) acc[mt][nt][r] = 0.0f;

    const int ar  = tid >> 1;          // 0..127
    const int ak  = (tid & 1) * 8;     // 0 or 8
    const bool aok = (row0 + ar) < M;
    const float* Ap = A  + (size_t)(row0 + ar) * K + ak;
    const float* Bp = Bt + (size_t)(col0 + ar) * K + ak;

    float4 ga0, ga1, gb0, gb1;
    auto gload = [&](int kbase) {
        if (aok) {
            ga0 = *(const float4*)(Ap + kbase);
            ga1 = *(const float4*)(Ap + kbase + 4);
        } else {
            ga0 = make_float4(0.f, 0.f, 0.f, 0.f);
            ga1 = ga0;
        }
        gb0 = *(const float4*)(Bp + kbase);
        gb1 = *(const float4*)(Bp + kbase + 4);
    };
    auto sstore = [&](int buf) {
        As[buf][ak + 0][ar] = f2tf32(ga0.x);
        As[buf][ak + 1][ar] = f2tf32(ga0.y);
        As[buf][ak + 2][ar] = f2tf32(ga0.z);
        As[buf][ak + 3][ar] = f2tf32(ga0.w);
        As[buf][ak + 4][ar] = f2tf32(ga1.x);
        As[buf][ak + 5][ar] = f2tf32(ga1.y);
        As[buf][ak + 6][ar] = f2tf32(ga1.z);
        As[buf][ak + 7][ar] = f2tf32(ga1.w);
        Bs[buf][ak + 0][ar] = f2tf32(gb0.x);
        Bs[buf][ak + 1][ar] = f2tf32(gb0.y);
        Bs[buf][ak + 2][ar] = f2tf32(gb0.z);
        Bs[buf][ak + 3][ar] = f2tf32(gb0.w);
        Bs[buf][ak + 4][ar] = f2tf32(gb1.x);
        Bs[buf][ak + 5][ar] = f2tf32(gb1.y);
        Bs[buf][ak + 6][ar] = f2tf32(gb1.z);
        Bs[buf][ak + 7][ar] = f2tf32(gb1.w);
    };
    auto compute = [&](int buf) {
#pragma unroll
        for (int ks = 0; ks < 2; ks++) {
            const int kb = ks * 8;
            uint32_t bfr[4][2];
#pragma unroll
            for (int nt = 0; nt < 4; nt++) {
                const int cn = wn + nt * 8 + g;
                bfr[nt][0] = Bs[buf][kb + c][cn];
                bfr[nt][1] = Bs[buf][kb + c + 4][cn];
            }
#pragma unroll
            for (int mt = 0; mt < 4; mt++) {
                const int rm = wm + mt * 16 + g;
                uint32_t afr[4];
                afr[0] = As[buf][kb + c][rm];
                afr[1] = As[buf][kb + c][rm + 8];
                afr[2] = As[buf][kb + c + 4][rm];
                afr[3] = As[buf][kb + c + 4][rm + 8];
#pragma unroll
                for (int nt = 0; nt < 4; nt++)
                    mma_tf32(acc[mt][nt], afr, bfr[nt]);
            }
        }
    };

    const int nstage = K >> 4;
    gload(0);
    sstore(0);
    __syncthreads();
    for (int s = 0; s < nstage; s++) {
        if (s + 1 < nstage) gload((s + 1) << 4);
        compute(s & 1);
        if (s + 1 < nstage) {
            sstore((s + 1) & 1);
            __syncthreads();
        }
    }

    // Epilogue: direct float2 stores
#pragma unroll
    for (int nt = 0; nt < 4; nt++) {
        const int colb = col0 + wn + nt * 8 + c * 2;
        const float b0v = __ldg(bias + colb);
        const float b1v = __ldg(bias + colb + 1);
#pragma unroll
        for (int mt = 0; mt < 4; mt++) {
            const int r0 = row0 + wm + mt * 16 + g;
            if (r0 < M) {
                float2 o = make_float2(acc[mt][nt][0] + b0v, acc[mt][nt][1] + b1v);
                *(float2*)(C + (size_t)r0 * N + colb) = o;
            }
            if (r0 + 8 < M) {
                float2 o = make_float2(acc[mt][nt][2] + b0v, acc[mt][nt][3] + b1v);
                *(float2*)(C + (size_t)(r0 + 8) * N + colb) = o;
            }
        }
    }
}

// ---------------------------------------------------------------------------
// FFMA SGEMM with bias (exact fp32): C[M,N] = A[M,K] @ B[K,N] + bias[N]
// NOTE: B is [K,N] row-major (NOT transposed) — round-3-validated contract.
// ---------------------------------------------------------------------------
__global__ __launch_bounds__(256, 2) void sgemm_bias_kernel(
    const float* __restrict__ A, const float* __restrict__ Bm,
    const float* __restrict__ bias, float* __restrict__ C,
    int M, int N, int K)
{
    __shared__ float As[8][128];
    __shared__ float Bs[8][128];

    const int tid  = threadIdx.x;
    const int row0 = blockIdx.y * 128;
    const int col0 = blockIdx.x * 128;
    const int tx   = tid & 15;
    const int ty   = tid >> 4;

    float acc[8][8];
#pragma unroll
    for (int i = 0; i < 8; i++)
#pragma unroll
        for (int j = 0; j < 8; j++) acc[i][j] = 0.0f;

    const int a_row = tid >> 1;
    const int a_col = (tid & 1) * 4;
    const int b_row = tid >> 5;
    const int b_col = (tid & 31) * 4;

    const bool a_ok = (row0 + a_row) < M;
    const float* Aptr = A + (size_t)(row0 + a_row) * K + a_col;
    const float* Bptr = Bm + (size_t)b_row * N + col0 + b_col;

    for (int k0 = 0; k0 < K; k0 += 8) {
        float4 av = a_ok ? *(const float4*)(Aptr + k0)
                         : make_float4(0.f, 0.f, 0.f, 0.f);
        float4 bv = *(const float4*)(Bptr + (size_t)k0 * N);

        As[a_col + 0][a_row] = av.x;
        As[a_col + 1][a_row] = av.y;
        As[a_col + 2][a_row] = av.z;
        As[a_col + 3][a_row] = av.w;
        *(float4*)&Bs[b_row][b_col] = bv;
        __syncthreads();

#pragma unroll
        for (int kk = 0; kk < 8; kk++) {
            float ar[8], br[8];
            *(float4*)&ar[0] = *(const float4*)&As[kk][ty * 8];
            *(float4*)&ar[4] = *(const float4*)&As[kk][ty * 8 + 4];
            *(float4*)&br[0] = *(const float4*)&Bs[kk][tx * 8];
            *(float4*)&br[4] = *(const float4*)&Bs[kk][tx * 8 + 4];
#pragma unroll
            for (int i = 0; i < 8; i++)
#pragma unroll
                for (int j = 0; j < 8; j++)
                    acc[i][j] = fmaf(ar[i], br[j], acc[i][j]);
        }
        __syncthreads();
    }

    float bj[8];
#pragma unroll
    for (int j = 0; j < 8; j++) bj[j] = bias[col0 + tx * 8 + j];

#pragma unroll
    for (int i = 0; i < 8; i++) {
        int r = row0 + ty * 8 + i;
        if (r < M) {
            float* Cp = C + (size_t)r * N + col0 + tx * 8;
            float4 o0, o1;
            o0.x = acc[i][0] + bj[0]; o0.y = acc[i][1] + bj[1];
            o0.z = acc[i][2] + bj[2]; o0.w = acc[i][3] + bj[3];
            o1.x = acc[i][4] + bj[4]; o1.y = acc[i][5] + bj[5];
            o1.z = acc[i][6] + bj[6]; o1.w = acc[i][7] + bj[7];
            *(float4*)(Cp + 0) = o0;
            *(float4*)(Cp + 4) = o1;
        }
    }
}

// ---------------------------------------------------------------------------
// Sampling + in-warp softmax: one warp per (b, q, h); lane = head-dim channel.
// SOAW row layout: [so (256) | aw logits (128)]  stride 384.
// ---------------------------------------------------------------------------
__global__ __launch_bounds__(256) void sample_kernel(
    const float* __restrict__ ref,    // [B, LQ, 4, 2]
    const float* __restrict__ v,      // [B, LV, H, HD]
    const float* __restrict__ soaw,   // [B*LQ, 384]
    float* __restrict__ acc_out)      // [B*LQ, 256]
{
    const int w    = blockIdx.x * 8 + (threadIdx.x >> 5);
    const int lane = threadIdx.x & 31;
    const int h    = w & 7;
    const int bq   = w >> 3;
    const int b    = bq >> 10;

    const float* row   = soaw + (size_t)bq * 384;
    const float* so_p  = row + h * 32;
    const float* aw_p  = row + 256 + h * 16;
    const float* ref_p = ref + (size_t)bq * 8;
    const float* vb    = v + (size_t)b * cfg::LV * cfg::D + h * 32 + lane;

    // In-warp softmax over 16 logits (xor-8/4/2/1 stays within 16-lane halves)
    float logit = (lane < 16) ? aw_p[lane] : -1e30f;
    float mx = logit;
#pragma unroll
    for (int off = 8; off >= 1; off >>= 1)
        mx = fmaxf(mx, __shfl_xor_sync(0xffffffffu, mx, off));
    float e = __expf(logit - mx);
    float ssum = e;
#pragma unroll
    for (int off = 8; off >= 1; off >>= 1)
        ssum += __shfl_xor_sync(0xffffffffu, ssum, off);
    const float wnorm = e / ssum;     // valid on lanes 0..15

    const int LHW[4]    = {100, 50, 25, 13};
    const int LSTART[4] = {0, 10000, 12500, 13125};

    float acc = 0.0f;
#pragma unroll
    for (int l = 0; l < 4; l++) {
        const int   Wl = LHW[l];
        const int   Hl = LHW[l];
        const float bx = ref_p[l * 2 + 0] * (float)Wl - 0.5f;
        const float by = ref_p[l * 2 + 1] * (float)Hl - 0.5f;
        const float* base = vb + (size_t)LSTART[l] * cfg::D;

#pragma unroll
        for (int p = 0; p < 4; p++) {
            const float x  = bx + so_p[(l * 4 + p) * 2 + 0];
            const float y  = by + so_p[(l * 4 + p) * 2 + 1];
            const float wt = __shfl_sync(0xffffffffu, wnorm, l * 4 + p);

            const float x0f = floorf(x), y0f = floorf(y);
            const int   ix0 = (int)x0f,  iy0 = (int)y0f;
            const float fx = x - x0f,    fy = y - y0f;

            const bool vx0 = (ix0 >= 0)     && (ix0 < Wl);
            const bool vx1 = (ix0 + 1 >= 0) && (ix0 + 1 < Wl);
            const bool vy0 = (iy0 >= 0)     && (iy0 < Hl);
            const bool vy1 = (iy0 + 1 >= 0) && (iy0 + 1 < Hl);

            float v00 = 0.f, v01 = 0.f, v10 = 0.f, v11 = 0.f;
            if (vy0) {
                const float* r0 = base + (size_t)(iy0 * Wl) * cfg::D;
                if (vx0) v00 = __ldg(r0 + (size_t)ix0 * cfg::D);
                if (vx1) v01 = __ldg(r0 + (size_t)(ix0 + 1) * cfg::D);
            }
            if (vy1) {
                const float* r1 = base + (size_t)((iy0 + 1) * Wl) * cfg::D;
                if (vx0) v10 = __ldg(r1 + (size_t)ix0 * cfg::D);
                if (vx1) v11 = __ldg(r1 + (size_t)(ix0 + 1) * cfg::D);
            }

            const float top = v00 * (1.f - fx) + v01 * fx;
            const float bot = v10 * (1.f - fx) + v11 * fx;
            acc = fmaf(wt, top * (1.f - fy) + bot * fy, acc);
        }
    }
    acc_out[(size_t)bq * 256 + h * 32 + lane] = acc;
}

// ---------------------------------------------------------------------------
// Launch
// ---------------------------------------------------------------------------
extern "C" void kernel_launch(void* const* d_in, const int* in_sizes, int n_in,
                              void* d_out, int out_size)
{
    const float* query = (const float*)d_in[0];   // [8,1024,256]
    const float* refp  = (const float*)d_in[1];   // [8,1024,4,2]
    const float* value = (const float*)d_in[2];   // [8,13294,256]
    // d_in[3] = value_spatial_shapes (compile-time constant)
    const float* so_w  = (const float*)d_in[4];   // [256,256]
    const float* so_b  = (const float*)d_in[5];
    const float* aw_w  = (const float*)d_in[6];   // [256,128]
    const float* aw_b  = (const float*)d_in[7];
    const float* vp_w  = (const float*)d_in[8];   // [256,256]
    const float* vp_b  = (const float*)d_in[9];
    const float* op_w  = (const float*)d_in[10];  // [256,256]
    const float* op_b  = (const float*)d_in[11];
    float* out = (float*)d_out;                   // [8,1024,256]

    float* scratch = nullptr;
    cudaGetSymbolAddress((void**)&scratch, g_scratch);
    float* sV    = scratch + cfg::OFF_V;
    float* sSOAW = scratch + cfg::OFF_SOAW;
    float* sACC  = scratch + cfg::OFF_ACC;
    float* sVPT  = scratch + cfg::OFF_VPT;
    float* sSAWT = scratch + cfg::OFF_SAWT;
    float* sBSA  = scratch + cfg::OFF_BSA;

    const int MQ = cfg::B * cfg::LQ;      // 8192
    const int MV = cfg::B * cfg::LV;      // 106352

    // 0) transposes for the tf32 GEMMs ([N,K] K-major); bias concat.
    //    op_w is NOT transposed — the FFMA sgemm consumes [K,N] directly.
    {
        dim3 blk(32, 8);
        transpose_kernel<<<dim3(8, 8), blk>>>(vp_w, sVPT, 256, 256);
        transpose_kernel<<<dim3(8, 8), blk>>>(so_w, sSAWT, 256, 256);
        transpose_kernel<<<dim3(4, 8), blk>>>(aw_w, sSAWT + 256 * 256, 256, 128);
        concat_bias_kernel<<<1, 384>>>(so_b, aw_b, sBSA);
    }
    // 1) v = value @ vp_w + vp_b   (tf32 tensor path)
    tf32_gemm_bias<<<dim3(2, (MV + 127) / 128), 256>>>(value, sVPT, vp_b, sV,
                                                       MV, 256, 256);
    // 2) soaw = query @ [so_w|aw_w] + [so_b|aw_b]
    tf32_gemm_bias<<<dim3(3, MQ / 128), 256>>>(query, sSAWT, sBSA, sSOAW,
                                               MQ, 384, 256);
    // 3) sampling (softmax folded in)
    {
        int warps = cfg::B * cfg::LQ * cfg::H;   // 65536
        sample_kernel<<<warps / 8, 256>>>(refp, sV, sSOAW, sACC);
    }
    // 4) out = ACC @ op_w + op_b   (exact fp32; op_w is [K,N] row-major)
    sgemm_bias_kernel<<<dim3(2, MQ / 128), 256>>>(sACC, op_w, op_b, out,
                                                  MQ, 256, 256);
}

// round 9
// speedup vs baseline: 2.0462x; 1.2700x over previous
#include <cuda_runtime.h>
#include <math.h>
#include <stdint.h>

// ---------------------------------------------------------------------------
// MSDeformableAttention — GB300 (plain sm_103 target: tcgen05 unavailable,
// legacy mma.sync tf32 tensor path)
//
//   1) tf32_gemm: v    = value @ vp_w + vp_b            -> V [B*LV, 256]
//   2) tf32_gemm: soaw = query @ [so_w | aw_w] + bias   -> SOAW [B*LQ, 384]
//      (dual-source B: cols [0,256) from so_w, [256,384) from aw_w — no
//       transpose / concat prep kernels; weights consumed in place as [K,N])
//   3) sample: in-warp softmax + bilinear gather        -> ACC [B*LQ, 256]
//   4) tf32_gemm: out = ACC @ op_w + op_b
//
// B=8, LQ=1024, LV=13294, D=256, H=8, HD=32, L=4, P=4
// levels (h=w,start): (100,0) (50,10000) (25,12500) (13,13125)
// ---------------------------------------------------------------------------

namespace cfg {
constexpr int B  = 8;
constexpr int LQ = 1024;
constexpr int LV = 13294;
constexpr int D  = 256;
constexpr int H  = 8;

constexpr size_t SZ_V    = (size_t)B * LV * D;      // 27,226,112
constexpr size_t SZ_SOAW = (size_t)B * LQ * 384;
constexpr size_t SZ_ACC  = (size_t)B * LQ * D;

constexpr size_t OFF_V    = 0;
constexpr size_t OFF_SOAW = OFF_V    + SZ_V;
constexpr size_t OFF_ACC  = OFF_SOAW + SZ_SOAW;
constexpr size_t SZ_TOT   = OFF_ACC  + SZ_ACC;      // ~32.5M floats (~130 MB)
}  // namespace cfg

__device__ float g_scratch[cfg::SZ_TOT];

// ---------------------------------------------------------------------------
__device__ __forceinline__ uint32_t f2tf32(float x) {
    uint32_t u;
    asm("cvt.rna.tf32.f32 %0, %1;" : "=r"(u) : "f"(x));
    return u;
}

__device__ __forceinline__ void mma_tf32(float d[4], const uint32_t a[4],
                                         const uint32_t b[2]) {
    asm volatile(
        "mma.sync.aligned.m16n8k8.row.col.f32.tf32.tf32.f32 "
        "{%0,%1,%2,%3}, {%4,%5,%6,%7}, {%8,%9}, {%0,%1,%2,%3};"
        : "+f"(d[0]), "+f"(d[1]), "+f"(d[2]), "+f"(d[3])
        : "r"(a[0]), "r"(a[1]), "r"(a[2]), "r"(a[3]), "r"(b[0]), "r"(b[1]));
}

// ---------------------------------------------------------------------------
// tf32 mma.sync GEMM with bias, dual B source:
//   C[M,N] = A[M,K] @ B[K,N] + bias[N]
// where columns [0,N0) come from (B0 rowstride ldB0, bias0) and columns
// [N0,N) from (B1 rowstride ldB1, bias1). Selection is per-CTA uniform
// (requires N0 % 128 == 0). B matrices are row-major [K, *] — used in place.
// 128x128 CTA, BK=16 double-buffered, 256 threads (8 warps, 64x32 each).
// Requires K % 16 == 0, N % 128 == 0; M guarded.
// ---------------------------------------------------------------------------
__global__ __launch_bounds__(256, 2) void tf32_gemm_dual(
    const float* __restrict__ A,
    const float* __restrict__ B0, int ldB0,
    const float* __restrict__ B1, int ldB1, int N0,
    const float* __restrict__ bias0, const float* __restrict__ bias1,
    float* __restrict__ C, int M, int N, int K)
{
    __shared__ uint32_t As[2][16][132];
    __shared__ uint32_t Bs[2][16][132];

    const int tid  = threadIdx.x;
    const int wid  = tid >> 5;
    const int lane = tid & 31;
    const int g    = lane >> 2;   // 0..7
    const int c    = lane & 3;    // 0..3
    const int row0 = blockIdx.y * 128;
    const int col0 = blockIdx.x * 128;
    const int wm   = (wid >> 2) * 64;   // warp m-offset (0/64)
    const int wn   = (wid & 3) * 32;    // warp n-offset (0/32/64/96)

    // CTA-uniform B-source selection
    const bool sel = (col0 >= N0);
    const float* Bbase  = sel ? (B1 + (col0 - N0)) : (B0 + col0);
    const int    ldB    = sel ? ldB1 : ldB0;
    const float* biasp  = sel ? (bias1 + (col0 - N0)) : (bias0 + col0);

    float acc[4][4][4];
#pragma unroll
    for (int mt = 0; mt < 4; mt++)
#pragma unroll
        for (int nt = 0; nt < 4; nt++)
#pragma unroll
            for (int r = 0; r < 4; r++) acc[mt][nt][r] = 0.0f;

    // A global-load mapping: thread covers 8 consecutive k for one row
    const int ar  = tid >> 1;          // 0..127
    const int ak  = (tid & 1) * 8;     // 0 or 8
    const bool aok = (row0 + ar) < M;
    const float* Ap = A + (size_t)(row0 + ar) * K + ak;

    // B global-load mapping: [16 k-rows x 128 cols] = 512 float4, 2/thread
    const int bk0 = tid >> 5;          // 0..7   (k-row of first float4)
    const int bc4 = tid & 31;          // 0..31  (float4 column)

    float4 ga0, ga1, gbv0, gbv1;
    auto gload = [&](int kbase) {
        if (aok) {
            ga0 = *(const float4*)(Ap + kbase);
            ga1 = *(const float4*)(Ap + kbase + 4);
        } else {
            ga0 = make_float4(0.f, 0.f, 0.f, 0.f);
            ga1 = ga0;
        }
        gbv0 = *(const float4*)(Bbase + (size_t)(kbase + bk0) * ldB + bc4 * 4);
        gbv1 = *(const float4*)(Bbase + (size_t)(kbase + bk0 + 8) * ldB + bc4 * 4);
    };
    auto sstore = [&](int buf) {
        As[buf][ak + 0][ar] = f2tf32(ga0.x);
        As[buf][ak + 1][ar] = f2tf32(ga0.y);
        As[buf][ak + 2][ar] = f2tf32(ga0.z);
        As[buf][ak + 3][ar] = f2tf32(ga0.w);
        As[buf][ak + 4][ar] = f2tf32(ga1.x);
        As[buf][ak + 5][ar] = f2tf32(ga1.y);
        As[buf][ak + 6][ar] = f2tf32(ga1.z);
        As[buf][ak + 7][ar] = f2tf32(ga1.w);
        uint4 b0 = make_uint4(f2tf32(gbv0.x), f2tf32(gbv0.y),
                              f2tf32(gbv0.z), f2tf32(gbv0.w));
        uint4 b1 = make_uint4(f2tf32(gbv1.x), f2tf32(gbv1.y),
                              f2tf32(gbv1.z), f2tf32(gbv1.w));
        *(uint4*)&Bs[buf][bk0][bc4 * 4]     = b0;
        *(uint4*)&Bs[buf][bk0 + 8][bc4 * 4] = b1;
    };
    auto compute = [&](int buf) {
#pragma unroll
        for (int ks = 0; ks < 2; ks++) {
            const int kb = ks * 8;
            uint32_t bfr[4][2];
#pragma unroll
            for (int nt = 0; nt < 4; nt++) {
                const int cn = wn + nt * 8 + g;
                bfr[nt][0] = Bs[buf][kb + c][cn];
                bfr[nt][1] = Bs[buf][kb + c + 4][cn];
            }
#pragma unroll
            for (int mt = 0; mt < 4; mt++) {
                const int rm = wm + mt * 16 + g;
                uint32_t afr[4];
                afr[0] = As[buf][kb + c][rm];
                afr[1] = As[buf][kb + c][rm + 8];
                afr[2] = As[buf][kb + c + 4][rm];
                afr[3] = As[buf][kb + c + 4][rm + 8];
#pragma unroll
                for (int nt = 0; nt < 4; nt++)
                    mma_tf32(acc[mt][nt], afr, bfr[nt]);
            }
        }
    };

    const int nstage = K >> 4;
    gload(0);
    sstore(0);
    __syncthreads();
    for (int s = 0; s < nstage; s++) {
        if (s + 1 < nstage) gload((s + 1) << 4);
        compute(s & 1);
        if (s + 1 < nstage) {
            sstore((s + 1) & 1);
            __syncthreads();
        }
    }

    // Epilogue: direct float2 stores
#pragma unroll
    for (int nt = 0; nt < 4; nt++) {
        const int cl  = wn + nt * 8 + c * 2;       // column local to tile
        const float b0v = __ldg(biasp + cl);
        const float b1v = __ldg(biasp + cl + 1);
#pragma unroll
        for (int mt = 0; mt < 4; mt++) {
            const int r0 = row0 + wm + mt * 16 + g;
            if (r0 < M) {
                float2 o = make_float2(acc[mt][nt][0] + b0v, acc[mt][nt][1] + b1v);
                *(float2*)(C + (size_t)r0 * N + col0 + cl) = o;
            }
            if (r0 + 8 < M) {
                float2 o = make_float2(acc[mt][nt][2] + b0v, acc[mt][nt][3] + b1v);
                *(float2*)(C + (size_t)(r0 + 8) * N + col0 + cl) = o;
            }
        }
    }
}

// ---------------------------------------------------------------------------
// Sampling + in-warp softmax: one warp per (b, q, h); lane = head-dim channel.
// SOAW row layout: [so (256) | aw logits (128)]  stride 384.
// ---------------------------------------------------------------------------
__global__ __launch_bounds__(256) void sample_kernel(
    const float* __restrict__ ref,    // [B, LQ, 4, 2]
    const float* __restrict__ v,      // [B, LV, H, HD]
    const float* __restrict__ soaw,   // [B*LQ, 384]
    float* __restrict__ acc_out)      // [B*LQ, 256]
{
    const int w    = blockIdx.x * 8 + (threadIdx.x >> 5);
    const int lane = threadIdx.x & 31;
    const int h    = w & 7;
    const int bq   = w >> 3;
    const int b    = bq >> 10;

    const float* row   = soaw + (size_t)bq * 384;
    const float* so_p  = row + h * 32;
    const float* aw_p  = row + 256 + h * 16;
    const float* ref_p = ref + (size_t)bq * 8;
    const float* vb    = v + (size_t)b * cfg::LV * cfg::D + h * 32 + lane;

    // In-warp softmax over 16 logits (xor-8/4/2/1 stays within 16-lane halves)
    float logit = (lane < 16) ? aw_p[lane] : -1e30f;
    float mx = logit;
#pragma unroll
    for (int off = 8; off >= 1; off >>= 1)
        mx = fmaxf(mx, __shfl_xor_sync(0xffffffffu, mx, off));
    float e = __expf(logit - mx);
    float ssum = e;
#pragma unroll
    for (int off = 8; off >= 1; off >>= 1)
        ssum += __shfl_xor_sync(0xffffffffu, ssum, off);
    const float wnorm = e / ssum;     // valid on lanes 0..15

    const int LHW[4]    = {100, 50, 25, 13};
    const int LSTART[4] = {0, 10000, 12500, 13125};

    float acc = 0.0f;
#pragma unroll
    for (int l = 0; l < 4; l++) {
        const int   Wl = LHW[l];
        const int   Hl = LHW[l];
        const float bx = ref_p[l * 2 + 0] * (float)Wl - 0.5f;
        const float by = ref_p[l * 2 + 1] * (float)Hl - 0.5f;
        const float* base = vb + (size_t)LSTART[l] * cfg::D;

#pragma unroll
        for (int p = 0; p < 4; p++) {
            const float x  = bx + so_p[(l * 4 + p) * 2 + 0];
            const float y  = by + so_p[(l * 4 + p) * 2 + 1];
            const float wt = __shfl_sync(0xffffffffu, wnorm, l * 4 + p);

            const float x0f = floorf(x), y0f = floorf(y);
            const int   ix0 = (int)x0f,  iy0 = (int)y0f;
            const float fx = x - x0f,    fy = y - y0f;

            const bool vx0 = (ix0 >= 0)     && (ix0 < Wl);
            const bool vx1 = (ix0 + 1 >= 0) && (ix0 + 1 < Wl);
            const bool vy0 = (iy0 >= 0)     && (iy0 < Hl);
            const bool vy1 = (iy0 + 1 >= 0) && (iy0 + 1 < Hl);

            float v00 = 0.f, v01 = 0.f, v10 = 0.f, v11 = 0.f;
            if (vy0) {
                const float* r0 = base + (size_t)(iy0 * Wl) * cfg::D;
                if (vx0) v00 = __ldg(r0 + (size_t)ix0 * cfg::D);
                if (vx1) v01 = __ldg(r0 + (size_t)(ix0 + 1) * cfg::D);
            }
            if (vy1) {
                const float* r1 = base + (size_t)((iy0 + 1) * Wl) * cfg::D;
                if (vx0) v10 = __ldg(r1 + (size_t)ix0 * cfg::D);
                if (vx1) v11 = __ldg(r1 + (size_t)(ix0 + 1) * cfg::D);
            }

            const float top = v00 * (1.f - fx) + v01 * fx;
            const float bot = v10 * (1.f - fx) + v11 * fx;
            acc = fmaf(wt, top * (1.f - fy) + bot * fy, acc);
        }
    }
    acc_out[(size_t)bq * 256 + h * 32 + lane] = acc;
}

// ---------------------------------------------------------------------------
// Launch
// ---------------------------------------------------------------------------
extern "C" void kernel_launch(void* const* d_in, const int* in_sizes, int n_in,
                              void* d_out, int out_size)
{
    const float* query = (const float*)d_in[0];   // [8,1024,256]
    const float* refp  = (const float*)d_in[1];   // [8,1024,4,2]
    const float* value = (const float*)d_in[2];   // [8,13294,256]
    // d_in[3] = value_spatial_shapes (compile-time constant)
    const float* so_w  = (const float*)d_in[4];   // [256,256]  [K,N]
    const float* so_b  = (const float*)d_in[5];
    const float* aw_w  = (const float*)d_in[6];   // [256,128]  [K,N]
    const float* aw_b  = (const float*)d_in[7];
    const float* vp_w  = (const float*)d_in[8];   // [256,256]  [K,N]
    const float* vp_b  = (const float*)d_in[9];
    const float* op_w  = (const float*)d_in[10];  // [256,256]  [K,N]
    const float* op_b  = (const float*)d_in[11];
    float* out = (float*)d_out;                   // [8,1024,256]

    float* scratch = nullptr;
    cudaGetSymbolAddress((void**)&scratch, g_scratch);
    float* sV    = scratch + cfg::OFF_V;
    float* sSOAW = scratch + cfg::OFF_SOAW;
    float* sACC  = scratch + cfg::OFF_ACC;

    const int MQ = cfg::B * cfg::LQ;      // 8192
    const int MV = cfg::B * cfg::LV;      // 106352

    // 1) v = value @ vp_w + vp_b
    tf32_gemm_dual<<<dim3(2, (MV + 127) / 128), 256>>>(
        value, vp_w, 256, vp_w, 256, 256, vp_b, vp_b, sV, MV, 256, 256);
    // 2) soaw = query @ [so_w | aw_w] + [so_b | aw_b]  (split at col 256)
    tf32_gemm_dual<<<dim3(3, MQ / 128), 256>>>(
        query, so_w, 256, aw_w, 128, 256, so_b, aw_b, sSOAW, MQ, 384, 256);
    // 3) sampling (softmax folded in)
    {
        int warps = cfg::B * cfg::LQ * cfg::H;   // 65536
        sample_kernel<<<warps / 8, 256>>>(refp, sV, sSOAW, sACC);
    }
    // 4) out = ACC @ op_w + op_b
    tf32_gemm_dual<<<dim3(2, MQ / 128), 256>>>(
        sACC, op_w, 256, op_w, 256, 256, op_b, op_b, out, MQ, 256, 256);
}

// round 10
// speedup vs baseline: 2.4698x; 1.2070x over previous
#include <cuda_runtime.h>
#include <math.h>
#include <stdint.h>

// ---------------------------------------------------------------------------
// MSDeformableAttention — GB300 (plain sm_103 target: tcgen05 unavailable,
// legacy mma.sync tf32 tensor path, ldmatrix fragment loads)
//
//   1) tf32_gemm: v    = value @ vp_w + vp_b            -> V [B*LV, 256]
//   2) tf32_gemm: soaw = query @ [so_w | aw_w] + bias   -> SOAW [B*LQ, 384]
//   3) sample: in-warp softmax + bilinear gather        -> ACC [B*LQ, 256]
//   4) tf32_gemm: out = ACC @ op_w + op_b
//
// B=8, LQ=1024, LV=13294, D=256, H=8, HD=32, L=4, P=4
// levels (h=w,start): (100,0) (50,10000) (25,12500) (13,13125)
// ---------------------------------------------------------------------------

namespace cfg {
constexpr int B  = 8;
constexpr int LQ = 1024;
constexpr int LV = 13294;
constexpr int D  = 256;
constexpr int H  = 8;

constexpr size_t SZ_V    = (size_t)B * LV * D;      // 27,226,112
constexpr size_t SZ_SOAW = (size_t)B * LQ * 384;
constexpr size_t SZ_ACC  = (size_t)B * LQ * D;

constexpr size_t OFF_V    = 0;
constexpr size_t OFF_SOAW = OFF_V    + SZ_V;
constexpr size_t OFF_ACC  = OFF_SOAW + SZ_SOAW;
constexpr size_t SZ_TOT   = OFF_ACC  + SZ_ACC;      // ~32.5M floats (~130 MB)
}  // namespace cfg

__device__ float g_scratch[cfg::SZ_TOT];

// ---------------------------------------------------------------------------
__device__ __forceinline__ uint32_t f2tf32(float x) {
    uint32_t u;
    asm("cvt.rna.tf32.f32 %0, %1;" : "=r"(u) : "f"(x));
    return u;
}

__device__ __forceinline__ void mma_tf32(float d[4], const uint32_t a[4],
                                         const uint32_t b[2]) {
    asm volatile(
        "mma.sync.aligned.m16n8k8.row.col.f32.tf32.tf32.f32 "
        "{%0,%1,%2,%3}, {%4,%5,%6,%7}, {%8,%9}, {%0,%1,%2,%3};"
        : "+f"(d[0]), "+f"(d[1]), "+f"(d[2]), "+f"(d[3])
        : "r"(a[0]), "r"(a[1]), "r"(a[2]), "r"(a[3]), "r"(b[0]), "r"(b[1]));
}

__device__ __forceinline__ void ldsm_x4(uint32_t& r0, uint32_t& r1,
                                        uint32_t& r2, uint32_t& r3,
                                        uint32_t saddr) {
    asm volatile(
        "ldmatrix.sync.aligned.m8n8.x4.shared.b16 {%0,%1,%2,%3}, [%4];"
        : "=r"(r0), "=r"(r1), "=r"(r2), "=r"(r3) : "r"(saddr));
}

// ---------------------------------------------------------------------------
// tf32 mma.sync GEMM with bias, dual B source:
//   C[M,N] = A[M,K] @ B[K,N] + bias[N]
// Columns [0,N0) from (B0, ldB0, bias0); [N0,N) from (B1, ldB1, bias1);
// selection per-CTA uniform (N0 % 128 == 0). B row-major [K,*], in place.
// 128x128 CTA, BK=16 double-buffered, 256 threads (8 warps, 64x32 each).
// Smem: fragment-oriented rows of 16 words with XOR chunk swizzle
//   q = (k>>2) ^ ((row>>1)&3); ldmatrix.x4 reads; conflict-free both ways.
// Requires K % 16 == 0, N % 128 == 0; M guarded.
// ---------------------------------------------------------------------------
__global__ __launch_bounds__(256, 2) void tf32_gemm_dual(
    const float* __restrict__ A,
    const float* __restrict__ B0, int ldB0,
    const float* __restrict__ B1, int ldB1, int N0,
    const float* __restrict__ bias0, const float* __restrict__ bias1,
    float* __restrict__ C, int M, int N, int K)
{
    __shared__ uint32_t As[2][128 * 16];   // [m][16 words, swizzled chunks]
    __shared__ uint32_t Bs[2][128 * 16];   // [n][16 words, swizzled chunks]

    const int tid  = threadIdx.x;
    const int wid  = tid >> 5;
    const int lane = tid & 31;
    const int row0 = blockIdx.y * 128;
    const int col0 = blockIdx.x * 128;
    const int wm   = (wid >> 2) * 64;   // warp m-offset (0/64)
    const int wn   = (wid & 3) * 32;    // warp n-offset (0/32/64/96)

    // CTA-uniform B-source selection
    const bool sel = (col0 >= N0);
    const float* Bbase = sel ? (B1 + (col0 - N0)) : (B0 + col0);
    const int    ldB   = sel ? ldB1 : ldB0;
    const float* biasp = sel ? (bias1 + (col0 - N0)) : (bias0 + col0);

    float acc[4][4][4];
#pragma unroll
    for (int mt = 0; mt < 4; mt++)
#pragma unroll
        for (int nt = 0; nt < 4; nt++)
#pragma unroll
            for (int r = 0; r < 4; r++) acc[mt][nt][r] = 0.0f;

    // ---- global-load mappings ----
    // A: thread covers one row, 8 consecutive k (2 x LDG.128)
    const int ar = tid >> 1;           // 0..127
    const int ak = (tid & 1) * 8;      // 0 or 8
    const bool aok = (row0 + ar) < M;
    const float* Ap = A + (size_t)(row0 + ar) * K + ak;
    // B: thread covers one n-column, 8 consecutive k (8 x LDG.32, coalesced)
    const int bn  = tid & 127;         // local n
    const int bkh = (tid >> 7) * 8;    // 0 or 8

    // ---- smem store offsets (words), chunk-swizzled ----
    const int a_sw  = (ar >> 1) & 3;
    const int a_c0  = ak >> 2;                         // 0 or 2
    const uint32_t a_off0 = ar * 16 + ((a_c0 ^ a_sw) << 2);
    const uint32_t a_off1 = ar * 16 + (((a_c0 + 1) ^ a_sw) << 2);
    const int b_sw  = (bn >> 1) & 3;
    const int b_c0  = bkh >> 2;                        // 0 or 2
    const uint32_t b_off0 = bn * 16 + ((b_c0 ^ b_sw) << 2);
    const uint32_t b_off1 = bn * 16 + (((b_c0 + 1) ^ b_sw) << 2);

    // ---- ldmatrix per-lane address components ----
    const uint32_t asBase = (uint32_t)__cvta_generic_to_shared(As);
    const uint32_t bsBase = (uint32_t)__cvta_generic_to_shared(Bs);
    // A: lanes 0-7 -> rows m..m+7 chunk-lo, 8-15 -> +8 chunk-lo,
    //    16-23 -> rows chunk-hi, 24-31 -> +8 chunk-hi
    int a_mrow[4], a_msw[4];
#pragma unroll
    for (int mt = 0; mt < 4; mt++) {
        a_mrow[mt] = wm + mt * 16 + (lane & 7) + ((lane >> 3) & 1) * 8;
        a_msw[mt]  = (a_mrow[mt] >> 1) & 3;
    }
    const int a_cadd = lane >> 4;            // 0 or 1
    // B: lanes 0-7 -> n..n+7 chunk-lo, 8-15 -> chunk-hi,
    //    16-23 -> n+8 chunk-lo, 24-31 -> n+8 chunk-hi
    int b_nrow[2], b_nsw[2];
#pragma unroll
    for (int p = 0; p < 2; p++) {
        b_nrow[p] = wn + p * 16 + (lane & 7) + ((lane >> 4) & 1) * 8;
        b_nsw[p]  = (b_nrow[p] >> 1) & 3;
    }
    const int b_cadd = (lane >> 3) & 1;      // 0 or 1

    float4 ga0, ga1;
    float bv[8];
    auto gload = [&](int kbase) {
        if (aok) {
            ga0 = *(const float4*)(Ap + kbase);
            ga1 = *(const float4*)(Ap + kbase + 4);
        } else {
            ga0 = make_float4(0.f, 0.f, 0.f, 0.f);
            ga1 = ga0;
        }
#pragma unroll
        for (int i = 0; i < 8; i++)
            bv[i] = Bbase[(size_t)(kbase + bkh + i) * ldB + bn];
    };
    auto sstore = [&](int buf) {
        *(uint4*)&As[buf][a_off0] = make_uint4(f2tf32(ga0.x), f2tf32(ga0.y),
                                               f2tf32(ga0.z), f2tf32(ga0.w));
        *(uint4*)&As[buf][a_off1] = make_uint4(f2tf32(ga1.x), f2tf32(ga1.y),
                                               f2tf32(ga1.z), f2tf32(ga1.w));
        *(uint4*)&Bs[buf][b_off0] = make_uint4(f2tf32(bv[0]), f2tf32(bv[1]),
                                               f2tf32(bv[2]), f2tf32(bv[3]));
        *(uint4*)&Bs[buf][b_off1] = make_uint4(f2tf32(bv[4]), f2tf32(bv[5]),
                                               f2tf32(bv[6]), f2tf32(bv[7]));
    };
    auto compute = [&](int buf) {
#pragma unroll
        for (int ks = 0; ks < 2; ks++) {
            const int cb = ks * 2;
            uint32_t bfr[4][2];
#pragma unroll
            for (int p = 0; p < 2; p++) {
                uint32_t w = (uint32_t)(b_nrow[p] * 16 +
                                        (((cb + b_cadd) ^ b_nsw[p]) << 2));
                uint32_t r0, r1, r2, r3;
                ldsm_x4(r0, r1, r2, r3,
                        bsBase + (buf * 2048u + w) * 4u);
                bfr[p * 2][0]     = r0;
                bfr[p * 2][1]     = r1;
                bfr[p * 2 + 1][0] = r2;
                bfr[p * 2 + 1][1] = r3;
            }
#pragma unroll
            for (int mt = 0; mt < 4; mt++) {
                uint32_t w = (uint32_t)(a_mrow[mt] * 16 +
                                        (((cb + a_cadd) ^ a_msw[mt]) << 2));
                uint32_t afr[4];
                ldsm_x4(afr[0], afr[1], afr[2], afr[3],
                        asBase + (buf * 2048u + w) * 4u);
#pragma unroll
                for (int nt = 0; nt < 4; nt++)
                    mma_tf32(acc[mt][nt], afr, bfr[nt]);
            }
        }
    };

    const int nstage = K >> 4;
    gload(0);
    sstore(0);
    __syncthreads();
    for (int s = 0; s < nstage; s++) {
        if (s + 1 < nstage) gload((s + 1) << 4);
        compute(s & 1);
        if (s + 1 < nstage) {
            sstore((s + 1) & 1);
            __syncthreads();
        }
    }

    // Epilogue: direct float2 stores
    const int g = lane >> 2;
    const int c = lane & 3;
#pragma unroll
    for (int nt = 0; nt < 4; nt++) {
        const int cl  = wn + nt * 8 + c * 2;       // column local to tile
        const float b0v = __ldg(biasp + cl);
        const float b1v = __ldg(biasp + cl + 1);
#pragma unroll
        for (int mt = 0; mt < 4; mt++) {
            const int r0 = row0 + wm + mt * 16 + g;
            if (r0 < M) {
                float2 o = make_float2(acc[mt][nt][0] + b0v, acc[mt][nt][1] + b1v);
                *(float2*)(C + (size_t)r0 * N + col0 + cl) = o;
            }
            if (r0 + 8 < M) {
                float2 o = make_float2(acc[mt][nt][2] + b0v, acc[mt][nt][3] + b1v);
                *(float2*)(C + (size_t)(r0 + 8) * N + col0 + cl) = o;
            }
        }
    }
}

// ---------------------------------------------------------------------------
// Sampling + in-warp softmax: one warp per (b, q, h); lane = head-dim channel.
// SOAW row layout: [so (256) | aw logits (128)]  stride 384.
// ---------------------------------------------------------------------------
__global__ __launch_bounds__(256) void sample_kernel(
    const float* __restrict__ ref,    // [B, LQ, 4, 2]
    const float* __restrict__ v,      // [B, LV, H, HD]
    const float* __restrict__ soaw,   // [B*LQ, 384]
    float* __restrict__ acc_out)      // [B*LQ, 256]
{
    const int w    = blockIdx.x * 8 + (threadIdx.x >> 5);
    const int lane = threadIdx.x & 31;
    const int h    = w & 7;
    const int bq   = w >> 3;
    const int b    = bq >> 10;

    const float* row   = soaw + (size_t)bq * 384;
    const float* so_p  = row + h * 32;
    const float* aw_p  = row + 256 + h * 16;
    const float* ref_p = ref + (size_t)bq * 8;
    const float* vb    = v + (size_t)b * cfg::LV * cfg::D + h * 32 + lane;

    // In-warp softmax over 16 logits (xor-8/4/2/1 stays within 16-lane halves)
    float logit = (lane < 16) ? aw_p[lane] : -1e30f;
    float mx = logit;
#pragma unroll
    for (int off = 8; off >= 1; off >>= 1)
        mx = fmaxf(mx, __shfl_xor_sync(0xffffffffu, mx, off));
    float e = __expf(logit - mx);
    float ssum = e;
#pragma unroll
    for (int off = 8; off >= 1; off >>= 1)
        ssum += __shfl_xor_sync(0xffffffffu, ssum, off);
    const float wnorm = e / ssum;     // valid on lanes 0..15

    const int LHW[4]    = {100, 50, 25, 13};
    const int LSTART[4] = {0, 10000, 12500, 13125};

    float acc = 0.0f;
#pragma unroll
    for (int l = 0; l < 4; l++) {
        const int   Wl = LHW[l];
        const int   Hl = LHW[l];
        const float bx = ref_p[l * 2 + 0] * (float)Wl - 0.5f;
        const float by = ref_p[l * 2 + 1] * (float)Hl - 0.5f;
        const float* base = vb + (size_t)LSTART[l] * cfg::D;

#pragma unroll
        for (int p = 0; p < 4; p++) {
            const float x  = bx + so_p[(l * 4 + p) * 2 + 0];
            const float y  = by + so_p[(l * 4 + p) * 2 + 1];
            const float wt = __shfl_sync(0xffffffffu, wnorm, l * 4 + p);

            const float x0f = floorf(x), y0f = floorf(y);
            const int   ix0 = (int)x0f,  iy0 = (int)y0f;
            const float fx = x - x0f,    fy = y - y0f;

            const bool vx0 = (ix0 >= 0)     && (ix0 < Wl);
            const bool vx1 = (ix0 + 1 >= 0) && (ix0 + 1 < Wl);
            const bool vy0 = (iy0 >= 0)     && (iy0 < Hl);
            const bool vy1 = (iy0 + 1 >= 0) && (iy0 + 1 < Hl);

            float v00 = 0.f, v01 = 0.f, v10 = 0.f, v11 = 0.f;
            if (vy0) {
                const float* r0 = base + (size_t)(iy0 * Wl) * cfg::D;
                if (vx0) v00 = __ldg(r0 + (size_t)ix0 * cfg::D);
                if (vx1) v01 = __ldg(r0 + (size_t)(ix0 + 1) * cfg::D);
            }
            if (vy1) {
                const float* r1 = base + (size_t)((iy0 + 1) * Wl) * cfg::D;
                if (vx0) v10 = __ldg(r1 + (size_t)ix0 * cfg::D);
                if (vx1) v11 = __ldg(r1 + (size_t)(ix0 + 1) * cfg::D);
            }

            const float top = v00 * (1.f - fx) + v01 * fx;
            const float bot = v10 * (1.f - fx) + v11 * fx;
            acc = fmaf(wt, top * (1.f - fy) + bot * fy, acc);
        }
    }
    acc_out[(size_t)bq * 256 + h * 32 + lane] = acc;
}

// ---------------------------------------------------------------------------
// Launch
// ---------------------------------------------------------------------------
extern "C" void kernel_launch(void* const* d_in, const int* in_sizes, int n_in,
                              void* d_out, int out_size)
{
    const float* query = (const float*)d_in[0];   // [8,1024,256]
    const float* refp  = (const float*)d_in[1];   // [8,1024,4,2]
    const float* value = (const float*)d_in[2];   // [8,13294,256]
    // d_in[3] = value_spatial_shapes (compile-time constant)
    const float* so_w  = (const float*)d_in[4];   // [256,256]  [K,N]
    const float* so_b  = (const float*)d_in[5];
    const float* aw_w  = (const float*)d_in[6];   // [256,128]  [K,N]
    const float* aw_b  = (const float*)d_in[7];
    const float* vp_w  = (const float*)d_in[8];   // [256,256]  [K,N]
    const float* vp_b  = (const float*)d_in[9];
    const float* op_w  = (const float*)d_in[10];  // [256,256]  [K,N]
    const float* op_b  = (const float*)d_in[11];
    float* out = (float*)d_out;                   // [8,1024,256]

    float* scratch = nullptr;
    cudaGetSymbolAddress((void**)&scratch, g_scratch);
    float* sV    = scratch + cfg::OFF_V;
    float* sSOAW = scratch + cfg::OFF_SOAW;
    float* sACC  = scratch + cfg::OFF_ACC;

    const int MQ = cfg::B * cfg::LQ;      // 8192
    const int MV = cfg::B * cfg::LV;      // 106352

    // 1) v = value @ vp_w + vp_b
    tf32_gemm_dual<<<dim3(2, (MV + 127) / 128), 256>>>(
        value, vp_w, 256, vp_w, 256, 256, vp_b, vp_b, sV, MV, 256, 256);
    // 2) soaw = query @ [so_w | aw_w] + [so_b | aw_b]  (split at col 256)
    tf32_gemm_dual<<<dim3(3, MQ / 128), 256>>>(
        query, so_w, 256, aw_w, 128, 256, so_b, aw_b, sSOAW, MQ, 384, 256);
    // 3) sampling (softmax folded in)
    {
        int warps = cfg::B * cfg::LQ * cfg::H;   // 65536
        sample_kernel<<<warps / 8, 256>>>(refp, sV, sSOAW, sACC);
    }
    // 4) out = ACC @ op_w + op_b
    tf32_gemm_dual<<<dim3(2, MQ / 128), 256>>>(
        sACC, op_w, 256, op_w, 256, 256, op_b, op_b, out, MQ, 256, 256);
}